// round 1
// baseline (speedup 1.0000x reference)
#include <cuda_runtime.h>

#define BATCH 4
#define T_SEQ 1024
#define CDIM  512
#define NH    8
#define HDIM  64
#define SCALE_F 0.125f

// Scratch (no cudaMalloc allowed)
__device__ float g_q[BATCH * NH * T_SEQ * HDIM];
__device__ float g_k[BATCH * NH * T_SEQ * HDIM];
__device__ float g_v[BATCH * NH * T_SEQ * HDIM];
__device__ float g_y[BATCH * T_SEQ * CDIM];

// ---------------------------------------------------------------------------
// GEMM: out[m][n] = sum_k A[m][k] * W[n][k] + bias[n]
// MODE 0: QKV projection, blockIdx.z selects (W,b,out); epilogue writes
//         head-transposed layout [B][H][T][HD] into g_q/g_k/g_v.
// MODE 1: output projection, A = g_y (internal), out row-major to d_out.
// ---------------------------------------------------------------------------
template <int MODE>
__global__ __launch_bounds__(256)
void gemm_kernel(const float* __restrict__ A,
                 const float* __restrict__ W0, const float* __restrict__ b0,
                 const float* __restrict__ W1, const float* __restrict__ b1,
                 const float* __restrict__ W2, const float* __restrict__ b2,
                 float* __restrict__ out_proj)
{
    __shared__ float a_sh[64][17];
    __shared__ float w_sh[64][17];

    const float* W;
    const float* bias;
    float* out;
    const float* Ain;
    if (MODE == 0) {
        int z = blockIdx.z;
        W    = (z == 0) ? W0 : (z == 1) ? W1 : W2;
        bias = (z == 0) ? b0 : (z == 1) ? b1 : b2;
        out  = (z == 0) ? g_q : (z == 1) ? g_k : g_v;
        Ain  = A;
    } else {
        W = W0; bias = b0; out = out_proj;
        Ain = g_y;
    }

    const int m0 = blockIdx.y * 64;
    const int n0 = blockIdx.x * 64;
    const int tid = threadIdx.x;
    const int tx = tid & 15;
    const int ty = tid >> 4;

    // loader mapping: 64 rows x 4 float4 per row
    const int lr = tid >> 2;
    const int lc = (tid & 3) * 4;

    float acc[4][4] = {};

    for (int k0 = 0; k0 < CDIM; k0 += 16) {
        float4 av = *(const float4*)&Ain[(size_t)(m0 + lr) * CDIM + k0 + lc];
        float4 wv = *(const float4*)&W[(size_t)(n0 + lr) * CDIM + k0 + lc];
        a_sh[lr][lc + 0] = av.x; a_sh[lr][lc + 1] = av.y;
        a_sh[lr][lc + 2] = av.z; a_sh[lr][lc + 3] = av.w;
        w_sh[lr][lc + 0] = wv.x; w_sh[lr][lc + 1] = wv.y;
        w_sh[lr][lc + 2] = wv.z; w_sh[lr][lc + 3] = wv.w;
        __syncthreads();
#pragma unroll
        for (int kk = 0; kk < 16; kk++) {
            float a[4], b[4];
#pragma unroll
            for (int i = 0; i < 4; i++) a[i] = a_sh[ty * 4 + i][kk];
#pragma unroll
            for (int j = 0; j < 4; j++) b[j] = w_sh[tx * 4 + j][kk];
#pragma unroll
            for (int i = 0; i < 4; i++)
#pragma unroll
                for (int j = 0; j < 4; j++)
                    acc[i][j] = fmaf(a[i], b[j], acc[i][j]);
        }
        __syncthreads();
    }

    float bj[4];
#pragma unroll
    for (int j = 0; j < 4; j++) bj[j] = bias[n0 + tx * 4 + j];

#pragma unroll
    for (int i = 0; i < 4; i++) {
        int m = m0 + ty * 4 + i;
#pragma unroll
        for (int j = 0; j < 4; j++) {
            int n = n0 + tx * 4 + j;
            float val = acc[i][j] + bj[j];
            if (MODE == 0) {
                int b_ = m >> 10, t = m & 1023;
                int h = n >> 6, d = n & 63;
                out[(((size_t)(b_ * NH + h)) * T_SEQ + t) * HDIM + d] = val;
            } else {
                out[(size_t)m * CDIM + n] = val;
            }
        }
    }
}

// ---------------------------------------------------------------------------
// Flash attention with fused bias + causal/column mask.
// Block: one (b,h) pair, one 64-row query tile. 256 threads, 4x4 microtiles.
// ---------------------------------------------------------------------------
__global__ __launch_bounds__(256)
void attn_kernel(const float* __restrict__ attn_bias)
{
    extern __shared__ float sh[];
    float* q_sh = sh;                 // [64][65]
    float* k_sh = q_sh + 64 * 65;     // [64][65]
    float* v_sh = k_sh + 64 * 65;     // [64][65]
    float* p_sh = v_sh + 64 * 65;     // [64][65]

    const int bh = blockIdx.y;
    const int h  = bh & (NH - 1);
    const int b_ = bh >> 3;
    const int qt = blockIdx.x;
    const int tid = threadIdx.x;
    const int tx = tid & 15;
    const int ty = tid >> 4;

    const float* qg = g_q + (size_t)bh * T_SEQ * HDIM;
    const float* kg = g_k + (size_t)bh * T_SEQ * HDIM;
    const float* vg = g_v + (size_t)bh * T_SEQ * HDIM;
    const float* bias_h = attn_bias + h * 64 * 64;

    // Load Q tile (64x64) vectorized
    for (int vi = tid; vi < 64 * 16; vi += 256) {
        int r = vi >> 4;
        int c = (vi & 15) * 4;
        float4 val = *(const float4*)&qg[(size_t)(qt * 64 + r) * HDIM + c];
        q_sh[r * 65 + c + 0] = val.x; q_sh[r * 65 + c + 1] = val.y;
        q_sh[r * 65 + c + 2] = val.z; q_sh[r * 65 + c + 3] = val.w;
    }

    float m_i[4], l_i[4], o[4][4];
#pragma unroll
    for (int i = 0; i < 4; i++) {
        m_i[i] = -1e30f;
        l_i[i] = 0.f;
#pragma unroll
        for (int j = 0; j < 4; j++) o[i][j] = 0.f;
    }

    for (int kt = 0; kt <= qt; kt++) {
        __syncthreads();  // previous PV done before overwriting K/V; Q visible
        for (int vi = tid; vi < 64 * 16; vi += 256) {
            int r = vi >> 4;
            int c = (vi & 15) * 4;
            float4 kv = *(const float4*)&kg[(size_t)(kt * 64 + r) * HDIM + c];
            float4 vv = *(const float4*)&vg[(size_t)(kt * 64 + r) * HDIM + c];
            k_sh[r * 65 + c + 0] = kv.x; k_sh[r * 65 + c + 1] = kv.y;
            k_sh[r * 65 + c + 2] = kv.z; k_sh[r * 65 + c + 3] = kv.w;
            v_sh[r * 65 + c + 0] = vv.x; v_sh[r * 65 + c + 1] = vv.y;
            v_sh[r * 65 + c + 2] = vv.z; v_sh[r * 65 + c + 3] = vv.w;
        }
        __syncthreads();

        // S = Q * K^T (64x64 tile)
        float s[4][4] = {};
#pragma unroll 8
        for (int d = 0; d < 64; d++) {
            float a[4], bb[4];
#pragma unroll
            for (int i = 0; i < 4; i++) a[i] = q_sh[(ty * 4 + i) * 65 + d];
#pragma unroll
            for (int j = 0; j < 4; j++) bb[j] = k_sh[(tx * 4 + j) * 65 + d];
#pragma unroll
            for (int i = 0; i < 4; i++)
#pragma unroll
                for (int j = 0; j < 4; j++)
                    s[i][j] = fmaf(a[i], bb[j], s[i][j]);
        }

        // scale + bias + mask
#pragma unroll
        for (int i = 0; i < 4; i++) {
            int qrow = qt * 64 + ty * 4 + i;
#pragma unroll
            for (int j = 0; j < 4; j++) {
                int kcol = kt * 64 + tx * 4 + j;
                float val = s[i][j] * SCALE_F;
                if (qrow < 512 && kcol < 512)
                    val += bias_h[((qrow >> 3) << 6) + (kcol >> 3)];
                if (kcol > qrow || (kcol & 15) == 15) val = -1e30f;
                s[i][j] = val;
            }
        }

        // online softmax (row reductions across the 16-lane tx group)
#pragma unroll
        for (int i = 0; i < 4; i++) {
            float rm = fmaxf(fmaxf(s[i][0], s[i][1]), fmaxf(s[i][2], s[i][3]));
#pragma unroll
            for (int off = 8; off >= 1; off >>= 1)
                rm = fmaxf(rm, __shfl_xor_sync(0xffffffffu, rm, off));
            float mn = fmaxf(m_i[i], rm);
            float alpha = __expf(m_i[i] - mn);
            float rs = 0.f;
#pragma unroll
            for (int j = 0; j < 4; j++) {
                s[i][j] = __expf(s[i][j] - mn);
                rs += s[i][j];
            }
#pragma unroll
            for (int off = 8; off >= 1; off >>= 1)
                rs += __shfl_xor_sync(0xffffffffu, rs, off);
            l_i[i] = l_i[i] * alpha + rs;
            m_i[i] = mn;
#pragma unroll
            for (int j = 0; j < 4; j++) {
                o[i][j] *= alpha;
                p_sh[(ty * 4 + i) * 65 + tx * 4 + j] = s[i][j];
            }
        }
        __syncthreads();

        // O += P * V
#pragma unroll 8
        for (int kk = 0; kk < 64; kk++) {
            float a[4], bb[4];
#pragma unroll
            for (int i = 0; i < 4; i++) a[i] = p_sh[(ty * 4 + i) * 65 + kk];
#pragma unroll
            for (int j = 0; j < 4; j++) bb[j] = v_sh[kk * 65 + tx * 4 + j];
#pragma unroll
            for (int i = 0; i < 4; i++)
#pragma unroll
                for (int j = 0; j < 4; j++)
                    o[i][j] = fmaf(a[i], bb[j], o[i][j]);
        }
    }

    // write y in (B, T, C) layout
#pragma unroll
    for (int i = 0; i < 4; i++) {
        float inv = 1.0f / l_i[i];
        int t = qt * 64 + ty * 4 + i;
        size_t base = ((size_t)(b_ * T_SEQ + t)) * CDIM + h * 64 + tx * 4;
#pragma unroll
        for (int j = 0; j < 4; j++)
            g_y[base + j] = o[i][j] * inv;
    }
}

// ---------------------------------------------------------------------------

extern "C" void kernel_launch(void* const* d_in, const int* in_sizes, int n_in,
                              void* d_out, int out_size)
{
    const float* x  = (const float*)d_in[0];
    const float* ab = (const float*)d_in[1];
    const float* Wq = (const float*)d_in[2];
    const float* bq = (const float*)d_in[3];
    const float* Wk = (const float*)d_in[4];
    const float* bk = (const float*)d_in[5];
    const float* Wv = (const float*)d_in[6];
    const float* bv = (const float*)d_in[7];
    const float* Wp = (const float*)d_in[8];
    const float* bp = (const float*)d_in[9];
    float* out = (float*)d_out;

    // QKV projections (z selects weight / destination)
    dim3 gq(CDIM / 64, (BATCH * T_SEQ) / 64, 3);
    gemm_kernel<0><<<gq, 256>>>(x, Wq, bq, Wk, bk, Wv, bv, nullptr);

    // Flash attention
    size_t smem = 4 * 64 * 65 * sizeof(float);
    cudaFuncSetAttribute(attn_kernel, cudaFuncAttributeMaxDynamicSharedMemorySize,
                         (int)smem);
    attn_kernel<<<dim3(T_SEQ / 64, BATCH * NH), 256, smem>>>(ab);

    // Output projection
    dim3 gp(CDIM / 64, (BATCH * T_SEQ) / 64, 1);
    gemm_kernel<1><<<gp, 256>>>(nullptr, Wp, bp, nullptr, nullptr, nullptr,
                                nullptr, out);
}

// round 3
// speedup vs baseline: 1.2927x; 1.2927x over previous
#include <cuda_runtime.h>

#define BATCH 4
#define T_SEQ 1024
#define CDIM  512
#define NH    8
#define HDIM  64
#define SCALE_F 0.125f

// Scratch (no cudaMalloc allowed)
__device__ float g_q[BATCH * NH * T_SEQ * HDIM];
__device__ float g_k[BATCH * NH * T_SEQ * HDIM];
__device__ float g_v[BATCH * NH * T_SEQ * HDIM];
__device__ float g_y[BATCH * T_SEQ * CDIM];

// ---------------------------------------------------------------------------
// GEMM: out[m][n] = sum_k A[m][k] * W[n][k] + bias[n]
// 128x128 tile, BK=16, 256 threads, 8x8 microtile, transposed smem staging.
// ---------------------------------------------------------------------------
template <int MODE>
__global__ __launch_bounds__(256, 2)
void gemm_kernel(const float* __restrict__ A,
                 const float* __restrict__ W0, const float* __restrict__ b0,
                 const float* __restrict__ W1, const float* __restrict__ b1,
                 const float* __restrict__ W2, const float* __restrict__ b2,
                 float* __restrict__ out_proj)
{
    __shared__ float a_sh[16][132];   // [k][m]  pitch 132 (16B-divisible)
    __shared__ float b_sh[16][132];   // [k][n]

    const float* W;
    const float* bias;
    float* out;
    const float* Ain;
    if (MODE == 0) {
        int z = blockIdx.z;
        W    = (z == 0) ? W0 : (z == 1) ? W1 : W2;
        bias = (z == 0) ? b0 : (z == 1) ? b1 : b2;
        out  = (z == 0) ? g_q : (z == 1) ? g_k : g_v;
        Ain  = A;
    } else {
        W = W0; bias = b0; out = out_proj;
        Ain = g_y;
    }

    const int m0 = blockIdx.y * 128;
    const int n0 = blockIdx.x * 128;
    const int tid = threadIdx.x;
    const int tx = tid & 15;
    const int ty = tid >> 4;

    const float* Aptr = Ain + (size_t)m0 * CDIM;
    const float* Wptr = W   + (size_t)n0 * CDIM;

    float4 ra[2], rb[2];

    // prefetch k-tile 0
#pragma unroll
    for (int l = 0; l < 2; l++) {
        int f = tid + l * 256;
        int row = f >> 2, kq = (f & 3) * 4;
        ra[l] = *(const float4*)&Aptr[(size_t)row * CDIM + kq];
        rb[l] = *(const float4*)&Wptr[(size_t)row * CDIM + kq];
    }

    float acc[8][8] = {};

    for (int kt = 0; kt < CDIM / 16; kt++) {
#pragma unroll
        for (int l = 0; l < 2; l++) {
            int f = tid + l * 256;
            int row = f >> 2, kq = (f & 3) * 4;
            a_sh[kq + 0][row] = ra[l].x; a_sh[kq + 1][row] = ra[l].y;
            a_sh[kq + 2][row] = ra[l].z; a_sh[kq + 3][row] = ra[l].w;
            b_sh[kq + 0][row] = rb[l].x; b_sh[kq + 1][row] = rb[l].y;
            b_sh[kq + 2][row] = rb[l].z; b_sh[kq + 3][row] = rb[l].w;
        }
        __syncthreads();

        if (kt < CDIM / 16 - 1) {
            int k0 = (kt + 1) * 16;
#pragma unroll
            for (int l = 0; l < 2; l++) {
                int f = tid + l * 256;
                int row = f >> 2, kq = (f & 3) * 4;
                ra[l] = *(const float4*)&Aptr[(size_t)row * CDIM + k0 + kq];
                rb[l] = *(const float4*)&Wptr[(size_t)row * CDIM + k0 + kq];
            }
        }

#pragma unroll
        for (int kk = 0; kk < 16; kk++) {
            float4 a0 = *(const float4*)&a_sh[kk][ty * 8];
            float4 a1 = *(const float4*)&a_sh[kk][ty * 8 + 4];
            float4 b0 = *(const float4*)&b_sh[kk][tx * 8];
            float4 b1 = *(const float4*)&b_sh[kk][tx * 8 + 4];
            float a[8] = {a0.x, a0.y, a0.z, a0.w, a1.x, a1.y, a1.z, a1.w};
            float b[8] = {b0.x, b0.y, b0.z, b0.w, b1.x, b1.y, b1.z, b1.w};
#pragma unroll
            for (int i = 0; i < 8; i++)
#pragma unroll
                for (int j = 0; j < 8; j++)
                    acc[i][j] = fmaf(a[i], b[j], acc[i][j]);
        }
        __syncthreads();
    }

    float bj[8];
    *(float4*)&bj[0] = *(const float4*)&bias[n0 + tx * 8];
    *(float4*)&bj[4] = *(const float4*)&bias[n0 + tx * 8 + 4];

#pragma unroll
    for (int i = 0; i < 8; i++) {
        int m = m0 + ty * 8 + i;
#pragma unroll
        for (int jj = 0; jj < 2; jj++) {
            int n = n0 + tx * 8 + jj * 4;
            float4 r;
            r.x = acc[i][jj * 4 + 0] + bj[jj * 4 + 0];
            r.y = acc[i][jj * 4 + 1] + bj[jj * 4 + 1];
            r.z = acc[i][jj * 4 + 2] + bj[jj * 4 + 2];
            r.w = acc[i][jj * 4 + 3] + bj[jj * 4 + 3];
            if (MODE == 0) {
                int b_ = m >> 10, t = m & 1023;
                int h = n >> 6, d = n & 63;
                *(float4*)&out[(((size_t)(b_ * NH + h)) * T_SEQ + t) * HDIM + d] = r;
            } else {
                *(float4*)&out[(size_t)m * CDIM + n] = r;
            }
        }
    }
}

// ---------------------------------------------------------------------------
// Flash attention, Br=Bc=128, 256 threads, 8x8 S-microtile, fused bias+mask.
// Q/K staged transposed [d][row] (pitch 132 -> 16B aligned float4 reads).
// ---------------------------------------------------------------------------
__global__ __launch_bounds__(256, 1)
void attn_kernel(const float* __restrict__ attn_bias)
{
    extern __shared__ float sh[];
    float* qT = sh;                 // [64][132]
    float* kT = sh + 64 * 132;      // [64][132]
    float* vs = sh + 2 * 64 * 132;  // [128][68]
    float* ps = vs + 128 * 68;      // [128][132]

    const int bh = blockIdx.y;
    const int h  = bh & (NH - 1);
    const int b_ = bh >> 3;
    const int qt = (int)(gridDim.x - 1) - (int)blockIdx.x;  // heavy tiles first
    const int tid = threadIdx.x;
    const int tx = tid & 15;
    const int ty = tid >> 4;

    const float* qg = g_q + (size_t)bh * T_SEQ * HDIM;
    const float* kg = g_k + (size_t)bh * T_SEQ * HDIM;
    const float* vg = g_v + (size_t)bh * T_SEQ * HDIM;
    const float* bias_h = attn_bias + h * 64 * 64;

    // Q tile -> transposed smem
#pragma unroll
    for (int l = 0; l < 8; l++) {
        int f = tid + l * 256;
        int row = f >> 4, dq = (f & 15) * 4;
        float4 v4 = *(const float4*)&qg[(size_t)(qt * 128 + row) * HDIM + dq];
        qT[(dq + 0) * 132 + row] = v4.x;
        qT[(dq + 1) * 132 + row] = v4.y;
        qT[(dq + 2) * 132 + row] = v4.z;
        qT[(dq + 3) * 132 + row] = v4.w;
    }

    float m_i[8], l_i[8], o[8][4];
#pragma unroll
    for (int i = 0; i < 8; i++) {
        m_i[i] = -1e30f;
        l_i[i] = 0.f;
#pragma unroll
        for (int j = 0; j < 4; j++) o[i][j] = 0.f;
    }

    for (int kt = 0; kt <= qt; kt++) {
        __syncthreads();   // prev PV done (and Q staged, first iter)
#pragma unroll
        for (int l = 0; l < 8; l++) {
            int f = tid + l * 256;
            int row = f >> 4, dq = (f & 15) * 4;
            float4 kv = *(const float4*)&kg[(size_t)(kt * 128 + row) * HDIM + dq];
            kT[(dq + 0) * 132 + row] = kv.x;
            kT[(dq + 1) * 132 + row] = kv.y;
            kT[(dq + 2) * 132 + row] = kv.z;
            kT[(dq + 3) * 132 + row] = kv.w;
            float4 vv = *(const float4*)&vg[(size_t)(kt * 128 + row) * HDIM + dq];
            *(float4*)&vs[row * 68 + dq] = vv;
        }
        // bias: qrow>>3 = qt*16+ty, kcol>>3 = kt*16+tx, constant per microtile
        float bv = 0.f;
        if (qt < 4 && kt < 4)
            bv = bias_h[(qt * 16 + ty) * 64 + kt * 16 + tx];
        __syncthreads();

        // S = Q K^T (128x128 tile)
        float s[8][8] = {};
#pragma unroll 4
        for (int d = 0; d < 64; d++) {
            float4 a0 = *(const float4*)&qT[d * 132 + ty * 8];
            float4 a1 = *(const float4*)&qT[d * 132 + ty * 8 + 4];
            float4 b0 = *(const float4*)&kT[d * 132 + tx * 8];
            float4 b1 = *(const float4*)&kT[d * 132 + tx * 8 + 4];
            float a[8] = {a0.x, a0.y, a0.z, a0.w, a1.x, a1.y, a1.z, a1.w};
            float b[8] = {b0.x, b0.y, b0.z, b0.w, b1.x, b1.y, b1.z, b1.w};
#pragma unroll
            for (int i = 0; i < 8; i++)
#pragma unroll
                for (int j = 0; j < 8; j++)
                    s[i][j] = fmaf(a[i], b[j], s[i][j]);
        }

        // scale + bias
#pragma unroll
        for (int i = 0; i < 8; i++)
#pragma unroll
            for (int j = 0; j < 8; j++)
                s[i][j] = s[i][j] * SCALE_F + bv;

        // column mask: kcol%16==15 <=> (tx odd && j==7)
        if (tx & 1) {
#pragma unroll
            for (int i = 0; i < 8; i++) s[i][7] = -1e30f;
        }
        // causal mask only on the diagonal tile
        if (kt == qt) {
#pragma unroll
            for (int i = 0; i < 8; i++) {
                int qrl = ty * 8 + i;
#pragma unroll
                for (int j = 0; j < 8; j++)
                    if (tx * 8 + j > qrl) s[i][j] = -1e30f;
            }
        }

        // online softmax (row reductions over the 16 tx lanes)
#pragma unroll
        for (int i = 0; i < 8; i++) {
            float rm = s[i][0];
#pragma unroll
            for (int j = 1; j < 8; j++) rm = fmaxf(rm, s[i][j]);
#pragma unroll
            for (int off = 8; off >= 1; off >>= 1)
                rm = fmaxf(rm, __shfl_xor_sync(0xffffffffu, rm, off));
            float mn = fmaxf(m_i[i], rm);
            float alpha = __expf(m_i[i] - mn);
            float rs = 0.f;
#pragma unroll
            for (int j = 0; j < 8; j++) {
                s[i][j] = __expf(s[i][j] - mn);
                rs += s[i][j];
            }
#pragma unroll
            for (int off = 8; off >= 1; off >>= 1)
                rs += __shfl_xor_sync(0xffffffffu, rs, off);
            l_i[i] = l_i[i] * alpha + rs;
            m_i[i] = mn;
            float4 p0 = {s[i][0], s[i][1], s[i][2], s[i][3]};
            float4 p1 = {s[i][4], s[i][5], s[i][6], s[i][7]};
            *(float4*)&ps[(ty * 8 + i) * 132 + tx * 8]     = p0;
            *(float4*)&ps[(ty * 8 + i) * 132 + tx * 8 + 4] = p1;
#pragma unroll
            for (int j = 0; j < 4; j++) o[i][j] *= alpha;
        }
        __syncthreads();

        // O += P V  (P read as float4 along k; V as float4 along d)
        for (int k = 0; k < 128; k += 4) {
            float4 v0 = *(const float4*)&vs[(k + 0) * 68 + tx * 4];
            float4 v1 = *(const float4*)&vs[(k + 1) * 68 + tx * 4];
            float4 v2 = *(const float4*)&vs[(k + 2) * 68 + tx * 4];
            float4 v3 = *(const float4*)&vs[(k + 3) * 68 + tx * 4];
#pragma unroll
            for (int i = 0; i < 8; i++) {
                float4 p4 = *(const float4*)&ps[(ty * 8 + i) * 132 + k];
                o[i][0] = fmaf(p4.x, v0.x, o[i][0]);
                o[i][1] = fmaf(p4.x, v0.y, o[i][1]);
                o[i][2] = fmaf(p4.x, v0.z, o[i][2]);
                o[i][3] = fmaf(p4.x, v0.w, o[i][3]);
                o[i][0] = fmaf(p4.y, v1.x, o[i][0]);
                o[i][1] = fmaf(p4.y, v1.y, o[i][1]);
                o[i][2] = fmaf(p4.y, v1.z, o[i][2]);
                o[i][3] = fmaf(p4.y, v1.w, o[i][3]);
                o[i][0] = fmaf(p4.z, v2.x, o[i][0]);
                o[i][1] = fmaf(p4.z, v2.y, o[i][1]);
                o[i][2] = fmaf(p4.z, v2.z, o[i][2]);
                o[i][3] = fmaf(p4.z, v2.w, o[i][3]);
                o[i][0] = fmaf(p4.w, v3.x, o[i][0]);
                o[i][1] = fmaf(p4.w, v3.y, o[i][1]);
                o[i][2] = fmaf(p4.w, v3.z, o[i][2]);
                o[i][3] = fmaf(p4.w, v3.w, o[i][3]);
            }
        }
    }

    // epilogue: y in (B, T, C) layout
#pragma unroll
    for (int i = 0; i < 8; i++) {
        float inv = 1.0f / l_i[i];
        int t = qt * 128 + ty * 8 + i;
        float4 r = {o[i][0] * inv, o[i][1] * inv, o[i][2] * inv, o[i][3] * inv};
        *(float4*)&g_y[((size_t)(b_ * T_SEQ + t)) * CDIM + h * 64 + tx * 4] = r;
    }
}

// ---------------------------------------------------------------------------

extern "C" void kernel_launch(void* const* d_in, const int* in_sizes, int n_in,
                              void* d_out, int out_size)
{
    const float* x  = (const float*)d_in[0];
    const float* ab = (const float*)d_in[1];
    const float* Wq = (const float*)d_in[2];
    const float* bq = (const float*)d_in[3];
    const float* Wk = (const float*)d_in[4];
    const float* bk = (const float*)d_in[5];
    const float* Wv = (const float*)d_in[6];
    const float* bv = (const float*)d_in[7];
    const float* Wp = (const float*)d_in[8];
    const float* bp = (const float*)d_in[9];
    float* out = (float*)d_out;

    // QKV projections
    dim3 gq(CDIM / 128, (BATCH * T_SEQ) / 128, 3);
    gemm_kernel<0><<<gq, 256>>>(x, Wq, bq, Wk, bk, Wv, bv, nullptr);

    // Flash attention
    size_t smem = (size_t)(2 * 64 * 132 + 128 * 68 + 128 * 132) * sizeof(float);
    cudaFuncSetAttribute(attn_kernel, cudaFuncAttributeMaxDynamicSharedMemorySize,
                         (int)smem);
    attn_kernel<<<dim3(T_SEQ / 128, BATCH * NH), 256, smem>>>(ab);

    // Output projection
    dim3 gp(CDIM / 128, (BATCH * T_SEQ) / 128, 1);
    gemm_kernel<1><<<gp, 256>>>(nullptr, Wp, bp, nullptr, nullptr, nullptr,
                                nullptr, out);
}